// round 3
// baseline (speedup 1.0000x reference)
#include <cuda_runtime.h>
#include <math.h>

#define B_DIM 32
#define T_SEQ 512
#define D_DIM 512
#define U_DIM 512
#define NG    2048                 // 4*U
#define M_TOT (B_DIM * T_SEQ)     // 16384

// ---------------- scratch (static device memory; no allocations) ----------------
__device__ float g_xg[2][B_DIM][T_SEQ][NG];        // input projections, both dirs (256 MB)
__device__ float g_hbuf[2][2][B_DIM][U_DIM];       // h double buffers per direction
__device__ float g_hb_out[B_DIM][T_SEQ][U_DIM];    // backward-direction outputs
__device__ volatile unsigned g_epoch;              // barrier epoch (monotonic across launches)
__device__ unsigned g_count;                       // barrier arrival counter (self-resetting)

#define NCTA        128
#define REC_THREADS 128
#define HS_STRIDE   516                            // 512 + 4 pad (2064B: 16B-aligned rows, bank-spread)
#define SMEM_REC    (2 * 32 * HS_STRIDE * 4)       // Us[32][516] + hs[32][516] = 132096 B

// ---------------- packed f32x2 helpers (FFMA2 — PTX-only on sm_103a) ----------------
__device__ __forceinline__ void fma2(unsigned long long& d,
                                     unsigned long long a,
                                     unsigned long long b)
{
    asm("fma.rn.f32x2 %0, %1, %2, %0;" : "+l"(d) : "l"(a), "l"(b));
}

__device__ __forceinline__ float2 unpack2(unsigned long long v)
{
    float2 f;
    asm("mov.b64 {%0, %1}, %2;" : "=f"(f.x), "=f"(f.y) : "l"(v));
    return f;
}

__device__ __forceinline__ float hsum2(unsigned long long v)
{
    float2 f = unpack2(v);
    return f.x + f.y;
}

// =================================================================================
// Kernel A: xg[dir] = x @ W[dir] + b[dir]     (M=16384, K=512, N=2048, fp32 SGEMM)
// 128x128 block tile, BK=8, 8x8 per thread, 256 threads, register prefetch.
// FFMA2 inner product: A tile stored DUPLICATED in smem so (a,a) pairs come
// straight from LDS.128; B pairs are naturally adjacent. Bit-exact fp32.
// =================================================================================
__global__ __launch_bounds__(256) void gemm_xg(
    const float* __restrict__ X,
    const float* __restrict__ Wf, const float* __restrict__ bf,
    const float* __restrict__ Wb, const float* __restrict__ bb)
{
    const int dir = blockIdx.z;
    const float* __restrict__ W    = dir ? Wb : Wf;
    const float* __restrict__ bias = dir ? bb : bf;

    __shared__ float As2[8][256];   // k-major, each A value duplicated: [k][2m]=[k][2m+1]
    __shared__ float Bs[8][128];

    const int tid   = threadIdx.x;
    const int mBase = blockIdx.x * 128;
    const int nBase = blockIdx.y * 128;

    const int aRow = tid >> 1;            // 0..127
    const int aK   = (tid & 1) * 4;       // 0 or 4
    const int bK   = tid >> 5;            // 0..7
    const int bN   = (tid & 31) * 4;      // 0..124

    const float* aPtr = X + (size_t)(mBase + aRow) * D_DIM + aK;
    const float* bPtr = W + (size_t)bK * NG + nBase + bN;

    float4 aReg = *(const float4*)aPtr;
    float4 bReg = *(const float4*)bPtr;

    // 8 m-rows x 4 n-pairs of packed accumulators
    unsigned long long acc2[8][4];
    #pragma unroll
    for (int i = 0; i < 8; i++)
        #pragma unroll
        for (int j = 0; j < 4; j++) acc2[i][j] = 0ull;

    const int ty = tid >> 4;    // 0..15
    const int tx = tid & 15;    // 0..15

    for (int kt = 0; kt < D_DIM; kt += 8) {
        *(float2*)&As2[aK + 0][2 * aRow] = make_float2(aReg.x, aReg.x);
        *(float2*)&As2[aK + 1][2 * aRow] = make_float2(aReg.y, aReg.y);
        *(float2*)&As2[aK + 2][2 * aRow] = make_float2(aReg.z, aReg.z);
        *(float2*)&As2[aK + 3][2 * aRow] = make_float2(aReg.w, aReg.w);
        *(float4*)&Bs[bK][bN] = bReg;
        __syncthreads();

        if (kt + 8 < D_DIM) {
            aReg = *(const float4*)(aPtr + kt + 8);
            bReg = *(const float4*)(bPtr + (size_t)(kt + 8) * NG);
        }

        #pragma unroll
        for (int k = 0; k < 8; k++) {
            // a dup-pairs: 4 x LDS.128, each = ((a_i,a_i),(a_{i+1},a_{i+1}))
            const ulonglong2 aq0 = *(const ulonglong2*)&As2[k][16 * ty + 0];
            const ulonglong2 aq1 = *(const ulonglong2*)&As2[k][16 * ty + 4];
            const ulonglong2 aq2 = *(const ulonglong2*)&As2[k][16 * ty + 8];
            const ulonglong2 aq3 = *(const ulonglong2*)&As2[k][16 * ty + 12];
            // b pairs: 2 x LDS.128 = 4 packed (b_{2j},b_{2j+1}) pairs
            const ulonglong2 bq0 = *(const ulonglong2*)&Bs[k][8 * tx + 0];
            const ulonglong2 bq1 = *(const ulonglong2*)&Bs[k][8 * tx + 4];

            unsigned long long ad[8] = {aq0.x, aq0.y, aq1.x, aq1.y,
                                        aq2.x, aq2.y, aq3.x, aq3.y};
            unsigned long long bd[4] = {bq0.x, bq0.y, bq1.x, bq1.y};
            #pragma unroll
            for (int i = 0; i < 8; i++)
                #pragma unroll
                for (int j = 0; j < 4; j++)
                    fma2(acc2[i][j], ad[i], bd[j]);
        }
        __syncthreads();
    }

    float* outp = &g_xg[dir][0][0][0];
    #pragma unroll
    for (int i = 0; i < 8; i++) {
        int m = mBase + ty * 8 + i;
        float* row = outp + (size_t)m * NG + nBase + tx * 8;
        #pragma unroll
        for (int j = 0; j < 4; j++) {
            float2 v = unpack2(acc2[i][j]);
            row[2 * j + 0] = v.x + bias[nBase + tx * 8 + 2 * j + 0];
            row[2 * j + 1] = v.y + bias[nBase + tx * 8 + 2 * j + 1];
        }
    }
}

// =================================================================================
// Device-wide barrier (epoch-based, self-resetting counter for graph replays)
// =================================================================================
__device__ __forceinline__ void gbar(unsigned target)
{
    __syncthreads();
    if (threadIdx.x == 0) {
        __threadfence();
        unsigned v = atomicAdd(&g_count, 1u);
        if (v == NCTA - 1u) {
            g_count = 0u;
            __threadfence();
            g_epoch = target;
        } else {
            while (g_epoch < target) { }
        }
        __threadfence();
    }
    __syncthreads();
}

__device__ __forceinline__ float sigm(float x) { return 1.0f / (1.0f + expf(-x)); }

// =================================================================================
// Kernel B: persistent bidirectional LSTM recurrence.
// 128 CTAs (64 per direction), 128 threads each. CTA owns 8 units x 32 batches.
// U slice resident in smem; h re-staged each step; c in registers.
// Inner dot products packed along K with FFMA2 (operands naturally contiguous).
// =================================================================================
__global__ __launch_bounds__(REC_THREADS, 1) void lstm_rec(
    const float* __restrict__ z,
    const float* __restrict__ Uf, const float* __restrict__ Ub,
    float* __restrict__ out)
{
    extern __shared__ float sm[];
    float* Us = sm;                        // [32 cols][HS_STRIDE]
    float* hs = sm + 32 * HS_STRIDE;       // [32 batches][HS_STRIDE]

    const int bid = blockIdx.x;
    const int dir = bid & 1;
    const int blk = bid >> 1;              // 0..63
    const int u0  = blk * 8;
    const int tid = threadIdx.x;
    const int bp  = tid >> 3;              // 0..15
    const int uu  = tid & 7;               // 0..7
    const int b0  = bp * 2, b1 = b0 + 1;
    const int ug  = u0 + uu;
    const float* __restrict__ Uw = dir ? Ub : Uf;

    unsigned ep = g_epoch;   // all CTAs read the same stable value at launch start

    // Load U slice into smem, transposed: Us[g*8+u][k] = Uw[k][g*512 + u0 + u]
    {
        int ci = tid & 31;
        int gg = ci >> 3;
        int ul = ci & 7;
        int cg = gg * U_DIM + u0 + ul;
        int k0 = (tid >> 5) * 128;
        const float* src = Uw + cg;
        float* dst = Us + ci * HS_STRIDE;
        for (int k = k0; k < k0 + 128; k++)
            dst[k] = src[(size_t)k * NG];
    }

    // init: h0 = c0 = z
    float c0s = z[b0 * U_DIM + ug];
    float c1s = z[b1 * U_DIM + ug];
    g_hbuf[dir][0][b0][ug] = c0s;
    g_hbuf[dir][0][b1][ug] = c1s;

    gbar(++ep);

    const float* up0 = Us + (0 * 8 + uu) * HS_STRIDE;
    const float* up1 = Us + (1 * 8 + uu) * HS_STRIDE;
    const float* up2 = Us + (2 * 8 + uu) * HS_STRIDE;
    const float* up3 = Us + (3 * 8 + uu) * HS_STRIDE;

    for (int s = 0; s < T_SEQ; s++) {
        const int buf = s & 1;

        // stage h (this direction) into smem
        const float4* hsrc = (const float4*)&g_hbuf[dir][buf][0][0];
        for (int i = tid; i < (B_DIM * U_DIM / 4); i += REC_THREADS) {
            float4 v = hsrc[i];
            int e = i * 4;
            *(float4*)&hs[(e >> 9) * HS_STRIDE + (e & 511)] = v;
        }

        const int tt = dir ? (T_SEQ - 1 - s) : s;
        float xg0[4], xg1[4];
        #pragma unroll
        for (int g = 0; g < 4; g++) {
            xg0[g] = g_xg[dir][b0][tt][g * U_DIM + ug];
            xg1[g] = g_xg[dir][b1][tt][g * U_DIM + ug];
        }
        __syncthreads();

        // packed accumulators: [gate] pairs over even/odd k
        unsigned long long a0[4] = {0ull, 0ull, 0ull, 0ull};
        unsigned long long a1[4] = {0ull, 0ull, 0ull, 0ull};
        const float* h0p = hs + b0 * HS_STRIDE;
        const float* h1p = hs + b1 * HS_STRIDE;

        #pragma unroll 2
        for (int k = 0; k < U_DIM; k += 4) {
            const ulonglong2 h0q = *(const ulonglong2*)(h0p + k);
            const ulonglong2 h1q = *(const ulonglong2*)(h1p + k);
            const ulonglong2 u0q = *(const ulonglong2*)(up0 + k);
            const ulonglong2 u1q = *(const ulonglong2*)(up1 + k);
            const ulonglong2 u2q = *(const ulonglong2*)(up2 + k);
            const ulonglong2 u3q = *(const ulonglong2*)(up3 + k);
            fma2(a0[0], h0q.x, u0q.x); fma2(a0[0], h0q.y, u0q.y);
            fma2(a0[1], h0q.x, u1q.x); fma2(a0[1], h0q.y, u1q.y);
            fma2(a0[2], h0q.x, u2q.x); fma2(a0[2], h0q.y, u2q.y);
            fma2(a0[3], h0q.x, u3q.x); fma2(a0[3], h0q.y, u3q.y);
            fma2(a1[0], h1q.x, u0q.x); fma2(a1[0], h1q.y, u0q.y);
            fma2(a1[1], h1q.x, u1q.x); fma2(a1[1], h1q.y, u1q.y);
            fma2(a1[2], h1q.x, u2q.x); fma2(a1[2], h1q.y, u2q.y);
            fma2(a1[3], h1q.x, u3q.x); fma2(a1[3], h1q.y, u3q.y);
        }

        // gates (Keras order i, f, c, o)
        float i0 = sigm(xg0[0] + hsum2(a0[0]));
        float f0 = sigm(xg0[1] + hsum2(a0[1]));
        float g0 = tanhf(xg0[2] + hsum2(a0[2]));
        float o0 = sigm(xg0[3] + hsum2(a0[3]));
        c0s = f0 * c0s + i0 * g0;
        float h0 = o0 * tanhf(c0s);

        float i1 = sigm(xg1[0] + hsum2(a1[0]));
        float f1 = sigm(xg1[1] + hsum2(a1[1]));
        float g1 = tanhf(xg1[2] + hsum2(a1[2]));
        float o1 = sigm(xg1[3] + hsum2(a1[3]));
        c1s = f1 * c1s + i1 * g1;
        float h1 = o1 * tanhf(c1s);

        g_hbuf[dir][buf ^ 1][b0][ug] = h0;
        g_hbuf[dir][buf ^ 1][b1][ug] = h1;

        if (dir == 0) {
            out[((size_t)b0 * T_SEQ + s) * U_DIM + ug] = h0;
            out[((size_t)b1 * T_SEQ + s) * U_DIM + ug] = h1;
        } else {
            g_hb_out[b0][tt][ug] = h0;
            g_hb_out[b1][tt][ug] = h1;
        }

        gbar(++ep);
    }
}

// =================================================================================
// Kernel C: out += backward outputs
// =================================================================================
__global__ void add_bwd(float* __restrict__ out)
{
    int i = blockIdx.x * blockDim.x + threadIdx.x;
    const int n4 = B_DIM * T_SEQ * U_DIM / 4;
    if (i < n4) {
        float4 a = ((float4*)out)[i];
        float4 b = ((const float4*)&g_hb_out[0][0][0])[i];
        a.x += b.x; a.y += b.y; a.z += b.z; a.w += b.w;
        ((float4*)out)[i] = a;
    }
}

// =================================================================================
extern "C" void kernel_launch(void* const* d_in, const int* in_sizes, int n_in,
                              void* d_out, int out_size)
{
    const float* x  = (const float*)d_in[0];
    const float* z  = (const float*)d_in[1];
    const float* Wf = (const float*)d_in[2];
    const float* Uf = (const float*)d_in[3];
    const float* bf = (const float*)d_in[4];
    const float* Wb = (const float*)d_in[5];
    const float* Ub = (const float*)d_in[6];
    const float* bb = (const float*)d_in[7];
    float* out = (float*)d_out;

    cudaFuncSetAttribute(lstm_rec, cudaFuncAttributeMaxDynamicSharedMemorySize, SMEM_REC);

    dim3 gg(M_TOT / 128, NG / 128, 2);
    gemm_xg<<<gg, 256>>>(x, Wf, bf, Wb, bb);
    lstm_rec<<<NCTA, REC_THREADS, SMEM_REC>>>(z, Uf, Ub, out);
    add_bwd<<<(B_DIM * T_SEQ * U_DIM / 4 + 255) / 256, 256>>>(out);
}

// round 4
// speedup vs baseline: 2.5744x; 2.5744x over previous
#include <cuda_runtime.h>
#include <math.h>
#include <stdint.h>

#define B_DIM 32
#define T_SEQ 512
#define D_DIM 512
#define U_DIM 512
#define NG    2048                 // 4*U
#define M_TOT (B_DIM * T_SEQ)     // 16384

// ---------------- scratch (static device memory; no allocations) ----------------
__device__ float g_xg[2][B_DIM][T_SEQ][NG];        // input projections, both dirs (256 MB)
__device__ float g_hbuf[2][2][B_DIM][U_DIM];       // h double buffers per direction (k-PERMUTED layout)
__device__ float g_hb_out[B_DIM][T_SEQ][U_DIM];    // backward-direction outputs
__device__ volatile unsigned g_epoch;              // barrier epoch (monotonic across launches)
__device__ unsigned g_count;                       // barrier arrival counter (self-resetting)

#define NCTA        128
#define REC_THREADS 128

// ---------------- tf32 helpers ----------------
__device__ __forceinline__ unsigned f2tf32(float f)
{
    unsigned r;
    asm("cvt.rna.tf32.f32 %0, %1;" : "=r"(r) : "f"(f));
    return r;
}

// D += A@B, m16n8k8, A row-major, B col-major, tf32 in / fp32 accum
__device__ __forceinline__ void mma8(float* c,
                                     unsigned a0, unsigned a1, unsigned a2, unsigned a3,
                                     unsigned b0, unsigned b1)
{
    asm("mma.sync.aligned.m16n8k8.row.col.f32.tf32.tf32.f32 "
        "{%0,%1,%2,%3},{%4,%5,%6,%7},{%8,%9},{%0,%1,%2,%3};"
        : "+f"(c[0]), "+f"(c[1]), "+f"(c[2]), "+f"(c[3])
        : "r"(a0), "r"(a1), "r"(a2), "r"(a3), "r"(b0), "r"(b1));
}

// k-permutation within each 8-block: positions 0,2,4,6 <- k%8 in {0..3}; 1,3,5,7 <- {4..7}
// => (pi(k), pi(k)+... ) consecutive floats = (k, k+4): one LDS.64 per frag pair.
__device__ __forceinline__ int perm8(int k)
{
    return (k & ~7) | ((k & 3) << 1) | ((k & 7) >> 2);
}

__device__ __forceinline__ float sigm(float x) { return 1.0f / (1.0f + expf(-x)); }

// =================================================================================
// Kernel A: xg[dir] = x @ W[dir] + b[dir]  — tf32 tensor-core GEMM
// 128x128 block tile, BK=16, 256 threads (8 warps, 2M x 4N -> warp tile 64x32).
// Smem K-major with stride 136 (== 8 mod 32): conflict-free fragment loads.
// =================================================================================
#define GS 136
__global__ __launch_bounds__(256) void gemm_xg(
    const float* __restrict__ X,
    const float* __restrict__ Wf, const float* __restrict__ bf,
    const float* __restrict__ Wb, const float* __restrict__ bb)
{
    const int dir = blockIdx.z;
    const float* __restrict__ W    = dir ? Wb : Wf;
    const float* __restrict__ bias = dir ? bb : bf;

    __shared__ float As[16][GS];   // [k][m]
    __shared__ float Bs[16][GS];   // [k][n]

    const int tid   = threadIdx.x;
    const int mBase = blockIdx.x * 128;
    const int nBase = blockIdx.y * 128;
    const int lane  = tid & 31, wid = tid >> 5;
    const int gid   = lane >> 2, tig = lane & 3;
    const int m0w   = (wid & 1) * 64;
    const int n0w   = (wid >> 1) * 32;

    // loaders
    const int aM  = tid >> 1;            // 0..127
    const int aK0 = (tid & 1) * 8;       // 0 or 8
    const int bK  = tid >> 4;            // 0..15
    const int bN0 = (tid & 15) * 8;      // 0..120

    const float* aP = X + (size_t)(mBase + aM) * D_DIM + aK0;
    const float* bP = W + (size_t)bK * NG + nBase + bN0;

    float4 a0r = *(const float4*)aP;
    float4 a1r = *(const float4*)(aP + 4);
    float4 b0r = *(const float4*)bP;
    float4 b1r = *(const float4*)(bP + 4);

    float acc[4][4][4];
    #pragma unroll
    for (int i = 0; i < 4; i++)
        #pragma unroll
        for (int j = 0; j < 4; j++)
            #pragma unroll
            for (int q = 0; q < 4; q++) acc[i][j][q] = 0.0f;

    for (int kt = 0; kt < D_DIM; kt += 16) {
        // store with tf32 rounding
        As[aK0 + 0][aM] = __uint_as_float(f2tf32(a0r.x));
        As[aK0 + 1][aM] = __uint_as_float(f2tf32(a0r.y));
        As[aK0 + 2][aM] = __uint_as_float(f2tf32(a0r.z));
        As[aK0 + 3][aM] = __uint_as_float(f2tf32(a0r.w));
        As[aK0 + 4][aM] = __uint_as_float(f2tf32(a1r.x));
        As[aK0 + 5][aM] = __uint_as_float(f2tf32(a1r.y));
        As[aK0 + 6][aM] = __uint_as_float(f2tf32(a1r.z));
        As[aK0 + 7][aM] = __uint_as_float(f2tf32(a1r.w));
        {
            float4 c0 = make_float4(__uint_as_float(f2tf32(b0r.x)), __uint_as_float(f2tf32(b0r.y)),
                                    __uint_as_float(f2tf32(b0r.z)), __uint_as_float(f2tf32(b0r.w)));
            float4 c1 = make_float4(__uint_as_float(f2tf32(b1r.x)), __uint_as_float(f2tf32(b1r.y)),
                                    __uint_as_float(f2tf32(b1r.z)), __uint_as_float(f2tf32(b1r.w)));
            *(float4*)&Bs[bK][bN0 + 0] = c0;
            *(float4*)&Bs[bK][bN0 + 4] = c1;
        }
        __syncthreads();

        if (kt + 16 < D_DIM) {
            a0r = *(const float4*)(aP + kt + 16);
            a1r = *(const float4*)(aP + kt + 20);
            b0r = *(const float4*)(bP + (size_t)(kt + 16) * NG);
            b1r = *(const float4*)(bP + (size_t)(kt + 16) * NG + 4);
        }

        #pragma unroll
        for (int kk = 0; kk < 16; kk += 8) {
            unsigned af[4][4], bfr[4][2];
            #pragma unroll
            for (int mf = 0; mf < 4; mf++) {
                int mr = m0w + mf * 16 + gid;
                af[mf][0] = __float_as_uint(As[kk + tig][mr]);
                af[mf][1] = __float_as_uint(As[kk + tig][mr + 8]);
                af[mf][2] = __float_as_uint(As[kk + tig + 4][mr]);
                af[mf][3] = __float_as_uint(As[kk + tig + 4][mr + 8]);
            }
            #pragma unroll
            for (int nf = 0; nf < 4; nf++) {
                int nr = n0w + nf * 8 + gid;
                bfr[nf][0] = __float_as_uint(Bs[kk + tig][nr]);
                bfr[nf][1] = __float_as_uint(Bs[kk + tig + 4][nr]);
            }
            #pragma unroll
            for (int mf = 0; mf < 4; mf++)
                #pragma unroll
                for (int nf = 0; nf < 4; nf++)
                    mma8(acc[mf][nf], af[mf][0], af[mf][1], af[mf][2], af[mf][3],
                         bfr[nf][0], bfr[nf][1]);
        }
        __syncthreads();
    }

    // epilogue: bias + store (c0,c1)->(row, 2tig), (c2,c3)->(row+8, 2tig)
    float* outp = &g_xg[dir][0][0][0];
    #pragma unroll
    for (int nf = 0; nf < 4; nf++) {
        int ncol = nBase + n0w + nf * 8 + 2 * tig;
        float2 bv = *(const float2*)&bias[ncol];
        #pragma unroll
        for (int mf = 0; mf < 4; mf++) {
            int r0 = mBase + m0w + mf * 16 + gid;
            float2 v0 = make_float2(acc[mf][nf][0] + bv.x, acc[mf][nf][1] + bv.y);
            float2 v1 = make_float2(acc[mf][nf][2] + bv.x, acc[mf][nf][3] + bv.y);
            *(float2*)(outp + (size_t)r0 * NG + ncol)       = v0;
            *(float2*)(outp + (size_t)(r0 + 8) * NG + ncol) = v1;
        }
    }
}

// =================================================================================
// Device-wide barrier (epoch-based, self-resetting counter for graph replays)
// =================================================================================
__device__ __forceinline__ void gbar(unsigned target)
{
    __syncthreads();
    if (threadIdx.x == 0) {
        __threadfence();
        unsigned v = atomicAdd(&g_count, 1u);
        if (v == NCTA - 1u) {
            g_count = 0u;
            __threadfence();
            g_epoch = target;
        } else {
            while (g_epoch < target) { }
        }
        __threadfence();
    }
    __syncthreads();
}

// =================================================================================
// Kernel B: persistent bidirectional LSTM recurrence — tf32 tensor cores.
// 128 CTAs (64/dir), 128 threads (4 warps). CTA owns 8 units (= 32 gate-cols).
// U slice resident in smem (n-major, k-permuted, stride 520 -> conflict-free LDS.64
// fragments). h staged per step from global (producer stores k-permuted, so the
// staging copy is linear float4 + tf32 cvt). Per step: M=32,N=32,K=512 via mma.
// Warp w: m-half = w&1 (16 batches), gate-pair = w>>1 -> warp tile m16 x n16.
// =================================================================================
#define US_STR 520
#define GP_STR 34
#define SMEM_REC ((2 * 32 * US_STR + 32 * GP_STR) * 4)

__global__ __launch_bounds__(REC_THREADS, 1) void lstm_rec(
    const float* __restrict__ z,
    const float* __restrict__ Uf, const float* __restrict__ Ub,
    float* __restrict__ out)
{
    extern __shared__ float sm[];
    float* Us = sm;                       // [32 local cols][US_STR]
    float* hs = sm + 32 * US_STR;         // [32 batches][US_STR]
    float* gp = sm + 64 * US_STR;         // [32 batches][GP_STR] gate preacts

    const int bid = blockIdx.x;
    const int dir = bid & 1;
    const int blk = bid >> 1;             // 0..63
    const int u0  = blk * 8;
    const int tid = threadIdx.x;
    const int lane = tid & 31, wid = tid >> 5;
    const int gid = lane >> 2, tig = lane & 3;
    const int g0 = (wid >> 1) * 2, g1 = g0 + 1;   // this warp's two gates
    const int r0 = (wid & 1) * 16 + gid;          // A-frag base row (batch)
    const float* __restrict__ Uw = dir ? Ub : Uf;

    unsigned ep = g_epoch;

    // ---- load U slice into smem: Us[localcol][perm8(k)] (tf32) ----
    {
        int ci = tid & 31;                // local col: gate(ci>>3) x unit(ci&7)
        int kc = tid >> 5;                // k chunk
        int g  = ci >> 3, uul = ci & 7;
        const float* src = Uw + (size_t)(g * U_DIM + u0 + uul);
        float* dst = Us + ci * US_STR;
        for (int k = kc * 128; k < kc * 128 + 128; k++)
            dst[perm8(k)] = __uint_as_float(f2tf32(src[(size_t)k * NG]));
    }

    // ---- init state: h0 = c0 = z; h stored k-PERMUTED in g_hbuf ----
    float cst[2];
    #pragma unroll
    for (int q = 0; q < 2; q++) {
        int p = tid + q * 128;
        int b = p >> 3, uu = p & 7;
        float zv = z[b * U_DIM + u0 + uu];
        cst[q] = zv;
        g_hbuf[dir][0][b][u0 + ((uu & 3) << 1) + (uu >> 2)] = zv;
    }

    gbar(++ep);

    const float* hrow0b = hs + r0 * US_STR;
    const float* hrow1b = hs + (r0 + 8) * US_STR;
    const float* urow0  = Us + (g0 * 8 + gid) * US_STR;
    const float* urow1  = Us + (g1 * 8 + gid) * US_STR;
    const float* xgbase = &g_xg[dir][0][0][0];

    for (int s = 0; s < T_SEQ; s++) {
        const int buf = s & 1;

        // stage h into smem (already permuted in global; just cvt to tf32)
        {
            const float4* hsrc = (const float4*)&g_hbuf[dir][buf][0][0];
            #pragma unroll 4
            for (int i = tid; i < (B_DIM * U_DIM / 4); i += REC_THREADS) {
                float4 v = hsrc[i];
                int e = i * 4;
                float4 w4;
                w4.x = __uint_as_float(f2tf32(v.x));
                w4.y = __uint_as_float(f2tf32(v.y));
                w4.z = __uint_as_float(f2tf32(v.z));
                w4.w = __uint_as_float(f2tf32(v.w));
                *(float4*)&hs[(e >> 9) * US_STR + (e & 511)] = w4;
            }
        }

        const int tt = dir ? (T_SEQ - 1 - s) : s;

        // init C fragments from xg (biases already folded in by gemm_xg)
        float c0f[4], c1f[4];
        {
            const float* xr0 = xgbase + ((size_t)r0 * T_SEQ + tt) * NG + u0 + 2 * tig;
            const float* xr1 = xgbase + ((size_t)(r0 + 8) * T_SEQ + tt) * NG + u0 + 2 * tig;
            float2 t;
            t = *(const float2*)(xr0 + g0 * U_DIM); c0f[0] = t.x; c0f[1] = t.y;
            t = *(const float2*)(xr1 + g0 * U_DIM); c0f[2] = t.x; c0f[3] = t.y;
            t = *(const float2*)(xr0 + g1 * U_DIM); c1f[0] = t.x; c1f[1] = t.y;
            t = *(const float2*)(xr1 + g1 * U_DIM); c1f[2] = t.x; c1f[3] = t.y;
        }
        __syncthreads();   // hs ready

        // mma over K=512 (64 k8 steps); frag pair loads are single LDS.64
        #pragma unroll 4
        for (int kb = 0; kb < 64; kb++) {
            int o = kb * 8 + 2 * tig;
            uint2 ar0 = *(const uint2*)(hrow0b + o);   // (a0, a2)
            uint2 ar1 = *(const uint2*)(hrow1b + o);   // (a1, a3)
            uint2 bu0 = *(const uint2*)(urow0 + o);    // (b0, b1) gate g0
            uint2 bu1 = *(const uint2*)(urow1 + o);    // (b0, b1) gate g1
            mma8(c0f, ar0.x, ar1.x, ar0.y, ar1.y, bu0.x, bu0.y);
            mma8(c1f, ar0.x, ar1.x, ar0.y, ar1.y, bu1.x, bu1.y);
        }

        // publish preactivations to smem
        *(float2*)&gp[r0 * GP_STR + g0 * 8 + 2 * tig]       = make_float2(c0f[0], c0f[1]);
        *(float2*)&gp[(r0 + 8) * GP_STR + g0 * 8 + 2 * tig] = make_float2(c0f[2], c0f[3]);
        *(float2*)&gp[r0 * GP_STR + g1 * 8 + 2 * tig]       = make_float2(c1f[0], c1f[1]);
        *(float2*)&gp[(r0 + 8) * GP_STR + g1 * 8 + 2 * tig] = make_float2(c1f[2], c1f[3]);
        __syncthreads();

        // gates (Keras order i,f,c,o) + state update + outputs
        #pragma unroll
        for (int q = 0; q < 2; q++) {
            int p = tid + q * 128;
            int b = p >> 3, uu = p & 7;
            const float* row = gp + b * GP_STR;
            float iv = sigm(row[uu]);
            float fv = sigm(row[8 + uu]);
            float cc = tanhf(row[16 + uu]);
            float ov = sigm(row[24 + uu]);
            cst[q] = fv * cst[q] + iv * cc;
            float hv = ov * tanhf(cst[q]);
            g_hbuf[dir][buf ^ 1][b][u0 + ((uu & 3) << 1) + (uu >> 2)] = hv;
            if (dir == 0)
                out[((size_t)b * T_SEQ + s) * U_DIM + u0 + uu] = hv;
            else
                g_hb_out[b][tt][u0 + uu] = hv;
        }

        gbar(++ep);
    }
}

// =================================================================================
// Kernel C: out += backward outputs
// =================================================================================
__global__ void add_bwd(float* __restrict__ out)
{
    int i = blockIdx.x * blockDim.x + threadIdx.x;
    const int n4 = B_DIM * T_SEQ * U_DIM / 4;
    if (i < n4) {
        float4 a = ((float4*)out)[i];
        float4 b = ((const float4*)&g_hb_out[0][0][0])[i];
        a.x += b.x; a.y += b.y; a.z += b.z; a.w += b.w;
        ((float4*)out)[i] = a;
    }
}

// =================================================================================
extern "C" void kernel_launch(void* const* d_in, const int* in_sizes, int n_in,
                              void* d_out, int out_size)
{
    const float* x  = (const float*)d_in[0];
    const float* z  = (const float*)d_in[1];
    const float* Wf = (const float*)d_in[2];
    const float* Uf = (const float*)d_in[3];
    const float* bf = (const float*)d_in[4];
    const float* Wb = (const float*)d_in[5];
    const float* Ub = (const float*)d_in[6];
    const float* bb = (const float*)d_in[7];
    float* out = (float*)d_out;

    cudaFuncSetAttribute(lstm_rec, cudaFuncAttributeMaxDynamicSharedMemorySize, SMEM_REC);

    dim3 gg(M_TOT / 128, NG / 128, 2);
    gemm_xg<<<gg, 256>>>(x, Wf, bf, Wb, bb);
    lstm_rec<<<NCTA, REC_THREADS, SMEM_REC>>>(z, Uf, Ub, out);
    add_bwd<<<(B_DIM * T_SEQ * U_DIM / 4 + 255) / 256, 256>>>(out);
}

// round 5
// speedup vs baseline: 4.4431x; 1.7259x over previous
#include <cuda_runtime.h>
#include <math.h>
#include <stdint.h>

#define B_DIM 32
#define T_SEQ 512
#define D_DIM 512
#define U_DIM 512
#define NG    2048                 // 4*U
#define M_TOT (B_DIM * T_SEQ)     // 16384

// ---------------- scratch (static device memory; no allocations) ----------------
__device__ float g_xg[2][B_DIM][T_SEQ][NG];        // input projections, both dirs (256 MB)
__device__ float g_hbuf[2][2][B_DIM][U_DIM];       // h double buffers (k-PERMUTED, tf32-rounded)
__device__ float g_hb_out[B_DIM][T_SEQ][U_DIM];    // backward-direction outputs
__device__ volatile unsigned g_epoch[2];           // per-direction barrier epoch
__device__ unsigned g_count[2];                    // per-direction arrival counter

#define NCTA_DIR    64
#define REC_THREADS 256

// ---------------- tf32 helpers ----------------
__device__ __forceinline__ unsigned f2tf32(float f)
{
    unsigned r;
    asm("cvt.rna.tf32.f32 %0, %1;" : "=r"(r) : "f"(f));
    return r;
}

// D += A@B, m16n8k8, A row-major, B col-major, tf32 in / fp32 accum
__device__ __forceinline__ void mma8(float* c,
                                     unsigned a0, unsigned a1, unsigned a2, unsigned a3,
                                     unsigned b0, unsigned b1)
{
    asm("mma.sync.aligned.m16n8k8.row.col.f32.tf32.tf32.f32 "
        "{%0,%1,%2,%3},{%4,%5,%6,%7},{%8,%9},{%0,%1,%2,%3};"
        : "+f"(c[0]), "+f"(c[1]), "+f"(c[2]), "+f"(c[3])
        : "r"(a0), "r"(a1), "r"(a2), "r"(a3), "r"(b0), "r"(b1));
}

// k-permutation within each 8-block: (pi(k),pi(k)+1) consecutive = (k, k+4)
__device__ __forceinline__ int perm8(int k)
{
    return (k & ~7) | ((k & 3) << 1) | ((k & 7) >> 2);
}

// ---------------- fast transcendentals (MUFU-based, saturation-safe) ----------------
__device__ __forceinline__ float fsigm(float x)
{
    return __fdividef(1.0f, 1.0f + __expf(-x));        // x->+inf: 1, x->-inf: 0
}
__device__ __forceinline__ float ftanh(float x)
{
    return 1.0f - __fdividef(2.0f, 1.0f + __expf(2.0f * x));  // saturates to +-1
}

// =================================================================================
// Kernel A: xg[dir] = x @ W[dir] + b[dir]  — tf32 tensor-core GEMM
// 128x128 block tile, BK=16, 256 threads (8 warps, warp tile 64x32).
// Double-buffered smem: one __syncthreads per K-tile.
// =================================================================================
#define GS 136
__global__ __launch_bounds__(256) void gemm_xg(
    const float* __restrict__ X,
    const float* __restrict__ Wf, const float* __restrict__ bf,
    const float* __restrict__ Wb, const float* __restrict__ bb)
{
    const int dir = blockIdx.z;
    const float* __restrict__ W    = dir ? Wb : Wf;
    const float* __restrict__ bias = dir ? bb : bf;

    __shared__ float As[2][16][GS];   // [buf][k][m]
    __shared__ float Bs[2][16][GS];   // [buf][k][n]

    const int tid   = threadIdx.x;
    const int mBase = blockIdx.x * 128;
    const int nBase = blockIdx.y * 128;
    const int lane  = tid & 31, wid = tid >> 5;
    const int gid   = lane >> 2, tig = lane & 3;
    const int m0w   = (wid & 1) * 64;
    const int n0w   = (wid >> 1) * 32;

    const int aM  = tid >> 1;            // 0..127
    const int aK0 = (tid & 1) * 8;       // 0 or 8
    const int bK  = tid >> 4;            // 0..15
    const int bN0 = (tid & 15) * 8;      // 0..120

    const float* aP = X + (size_t)(mBase + aM) * D_DIM + aK0;
    const float* bP = W + (size_t)bK * NG + nBase + bN0;

    float4 a0r = *(const float4*)aP;
    float4 a1r = *(const float4*)(aP + 4);
    float4 b0r = *(const float4*)bP;
    float4 b1r = *(const float4*)(bP + 4);

    float acc[4][4][4];
    #pragma unroll
    for (int i = 0; i < 4; i++)
        #pragma unroll
        for (int j = 0; j < 4; j++)
            #pragma unroll
            for (int q = 0; q < 4; q++) acc[i][j][q] = 0.0f;

    // prologue: fill buffer 0
    As[0][aK0 + 0][aM] = __uint_as_float(f2tf32(a0r.x));
    As[0][aK0 + 1][aM] = __uint_as_float(f2tf32(a0r.y));
    As[0][aK0 + 2][aM] = __uint_as_float(f2tf32(a0r.z));
    As[0][aK0 + 3][aM] = __uint_as_float(f2tf32(a0r.w));
    As[0][aK0 + 4][aM] = __uint_as_float(f2tf32(a1r.x));
    As[0][aK0 + 5][aM] = __uint_as_float(f2tf32(a1r.y));
    As[0][aK0 + 6][aM] = __uint_as_float(f2tf32(a1r.z));
    As[0][aK0 + 7][aM] = __uint_as_float(f2tf32(a1r.w));
    {
        float4 c0 = make_float4(__uint_as_float(f2tf32(b0r.x)), __uint_as_float(f2tf32(b0r.y)),
                                __uint_as_float(f2tf32(b0r.z)), __uint_as_float(f2tf32(b0r.w)));
        float4 c1 = make_float4(__uint_as_float(f2tf32(b1r.x)), __uint_as_float(f2tf32(b1r.y)),
                                __uint_as_float(f2tf32(b1r.z)), __uint_as_float(f2tf32(b1r.w)));
        *(float4*)&Bs[0][bK][bN0 + 0] = c0;
        *(float4*)&Bs[0][bK][bN0 + 4] = c1;
    }
    __syncthreads();

    int cur = 0;
    for (int kt = 0; kt < D_DIM; kt += 16) {
        const bool more = (kt + 16 < D_DIM);
        if (more) {
            a0r = *(const float4*)(aP + kt + 16);
            a1r = *(const float4*)(aP + kt + 20);
            b0r = *(const float4*)(bP + (size_t)(kt + 16) * NG);
            b1r = *(const float4*)(bP + (size_t)(kt + 16) * NG + 4);
        }

        #pragma unroll
        for (int kk = 0; kk < 16; kk += 8) {
            unsigned af[4][4], bfr[4][2];
            #pragma unroll
            for (int mf = 0; mf < 4; mf++) {
                int mr = m0w + mf * 16 + gid;
                af[mf][0] = __float_as_uint(As[cur][kk + tig][mr]);
                af[mf][1] = __float_as_uint(As[cur][kk + tig][mr + 8]);
                af[mf][2] = __float_as_uint(As[cur][kk + tig + 4][mr]);
                af[mf][3] = __float_as_uint(As[cur][kk + tig + 4][mr + 8]);
            }
            #pragma unroll
            for (int nf = 0; nf < 4; nf++) {
                int nr = n0w + nf * 8 + gid;
                bfr[nf][0] = __float_as_uint(Bs[cur][kk + tig][nr]);
                bfr[nf][1] = __float_as_uint(Bs[cur][kk + tig + 4][nr]);
            }
            #pragma unroll
            for (int mf = 0; mf < 4; mf++)
                #pragma unroll
                for (int nf = 0; nf < 4; nf++)
                    mma8(acc[mf][nf], af[mf][0], af[mf][1], af[mf][2], af[mf][3],
                         bfr[nf][0], bfr[nf][1]);
        }

        if (more) {
            int nxt = cur ^ 1;
            As[nxt][aK0 + 0][aM] = __uint_as_float(f2tf32(a0r.x));
            As[nxt][aK0 + 1][aM] = __uint_as_float(f2tf32(a0r.y));
            As[nxt][aK0 + 2][aM] = __uint_as_float(f2tf32(a0r.z));
            As[nxt][aK0 + 3][aM] = __uint_as_float(f2tf32(a0r.w));
            As[nxt][aK0 + 4][aM] = __uint_as_float(f2tf32(a1r.x));
            As[nxt][aK0 + 5][aM] = __uint_as_float(f2tf32(a1r.y));
            As[nxt][aK0 + 6][aM] = __uint_as_float(f2tf32(a1r.z));
            As[nxt][aK0 + 7][aM] = __uint_as_float(f2tf32(a1r.w));
            float4 c0 = make_float4(__uint_as_float(f2tf32(b0r.x)), __uint_as_float(f2tf32(b0r.y)),
                                    __uint_as_float(f2tf32(b0r.z)), __uint_as_float(f2tf32(b0r.w)));
            float4 c1 = make_float4(__uint_as_float(f2tf32(b1r.x)), __uint_as_float(f2tf32(b1r.y)),
                                    __uint_as_float(f2tf32(b1r.z)), __uint_as_float(f2tf32(b1r.w)));
            *(float4*)&Bs[nxt][bK][bN0 + 0] = c0;
            *(float4*)&Bs[nxt][bK][bN0 + 4] = c1;
            __syncthreads();
            cur = nxt;
        }
    }

    float* outp = &g_xg[dir][0][0][0];
    #pragma unroll
    for (int nf = 0; nf < 4; nf++) {
        int ncol = nBase + n0w + nf * 8 + 2 * tig;
        float2 bv = *(const float2*)&bias[ncol];
        #pragma unroll
        for (int mf = 0; mf < 4; mf++) {
            int r0 = mBase + m0w + mf * 16 + gid;
            float2 v0 = make_float2(acc[mf][nf][0] + bv.x, acc[mf][nf][1] + bv.y);
            float2 v1 = make_float2(acc[mf][nf][2] + bv.x, acc[mf][nf][3] + bv.y);
            *(float2*)(outp + (size_t)r0 * NG + ncol)       = v0;
            *(float2*)(outp + (size_t)(r0 + 8) * NG + ncol) = v1;
        }
    }
}

// =================================================================================
// Kernel B: persistent bidirectional LSTM recurrence — tf32 tensor cores.
// 128 CTAs (64/dir), 256 threads (8 warps). CTA owns 8 units (= 32 gate-cols).
// Split-K: warps 0-3 (threads 0-127) own K<256, warps 4-7 own K>=256; each half
// stages its own K-range of h via cp.async (2 sub-chunks, pipelined with mma) and
// syncs on its own named barrier. Partials reduced in epilogue (+ xg, prefetched).
// =================================================================================
#define US_STR 520
#define GP_STR 34
#define SMEM_REC ((2 * 32 * US_STR + 2 * 32 * GP_STR) * 4)

__global__ __launch_bounds__(REC_THREADS, 1) void lstm_rec(
    const float* __restrict__ z,
    const float* __restrict__ Uf, const float* __restrict__ Ub,
    float* __restrict__ out)
{
    extern __shared__ float sm[];
    float* Us = sm;                       // [32 local cols][US_STR] (k-permuted tf32)
    float* hs = sm + 32 * US_STR;         // [32 batches][US_STR]   (k-permuted tf32)
    float* gp = sm + 64 * US_STR;         // [2 khalf][32 batches][GP_STR] partial preacts

    const int bid = blockIdx.x;
    const int dir = bid & 1;
    const int blk = bid >> 1;             // 0..63
    const int u0  = blk * 8;
    const int tid = threadIdx.x;
    const int lane = tid & 31, wid = tid >> 5;
    const int gid = lane >> 2, tig = lane & 3;
    const int mhalf = wid & 1;
    const int gpair = (wid >> 1) & 1;
    const int khalf = wid >> 2;           // threads 0-127: 0, 128-255: 1
    const int g0 = gpair * 2, g1 = g0 + 1;
    const int r0 = mhalf * 16 + gid;
    const int lt = tid & 127;             // index within K-half group
    const float* __restrict__ Uw = dir ? Ub : Uf;

    const unsigned ep0 = g_epoch[dir];

    // ---- load U slice into smem: Us[localcol][perm8(k)] (tf32), 256 threads ----
    {
        int ci = tid & 31;                // local col: gate(ci>>3) x unit(ci&7)
        int kc = tid >> 5;                // k chunk (0..7), 64 k each
        int g  = ci >> 3, uul = ci & 7;
        const float* src = Uw + (size_t)(g * U_DIM + u0 + uul);
        float* dst = Us + ci * US_STR;
        for (int k = kc * 64; k < kc * 64 + 64; k++)
            dst[perm8(k)] = __uint_as_float(f2tf32(src[(size_t)k * NG]));
    }

    // ---- init state: h0 = c0 = z; h stored k-PERMUTED + tf32-rounded ----
    float cst;
    {
        int b = tid >> 3, uu = tid & 7;
        float zv = z[b * U_DIM + u0 + uu];
        cst = zv;
        g_hbuf[dir][0][b][u0 + ((uu & 3) << 1) + (uu >> 2)] = __uint_as_float(f2tf32(zv));
    }
    __syncthreads();
    if (tid == 0) {
        __threadfence();
        unsigned v = atomicAdd(&g_count[dir], 1u);
        if (v == NCTA_DIR - 1u) {
            g_count[dir] = 0u;
            __threadfence();
            g_epoch[dir] = ep0 + 1u;
        }
    }

    const float* hrow0 = hs + r0 * US_STR;
    const float* hrow1 = hs + (r0 + 8) * US_STR;
    const float* urow0 = Us + (g0 * 8 + gid) * US_STR;
    const float* urow1 = Us + (g1 * 8 + gid) * US_STR;
    float* gpb = gp + khalf * 32 * GP_STR;
    const float* xgbase = &g_xg[dir][0][0][0];
    const unsigned hs_s = (unsigned)__cvta_generic_to_shared(hs);
    const int eb = tid >> 3, euu = tid & 7;           // epilogue (batch, unit)

    for (int s = 0; s < T_SEQ; s++) {
        const int buf = s & 1;
        const int tt  = dir ? (T_SEQ - 1 - s) : s;

        // prefetch xg for this step (independent of barrier; hides under spin)
        float xr[4];
        {
            const float* xp = xgbase + ((size_t)eb * T_SEQ + tt) * NG + u0 + euu;
            xr[0] = xp[0];
            xr[1] = xp[U_DIM];
            xr[2] = xp[2 * U_DIM];
            xr[3] = xp[3 * U_DIM];
        }

        // wait for h(s) to be globally visible
        if (tid == 0) {
            const unsigned target = ep0 + 1u + (unsigned)s;
            while (g_epoch[dir] < target) { }
        }
        __syncthreads();

        // stage this K-half of h into smem: 2 sub-chunks of 128 k, cp.async 16B
        const float* hsrcBase = &g_hbuf[dir][buf][0][0];
        #pragma unroll
        for (int q = 0; q < 2; q++) {
            const int kq = khalf * 256 + q * 128;
            #pragma unroll
            for (int j = 0; j < 8; j++) {
                int idx = j * 128 + lt;           // 0..1023
                int b   = idx >> 5;
                int k   = kq + (idx & 31) * 4;
                const float* src = hsrcBase + b * U_DIM + k;
                unsigned dst = hs_s + (unsigned)(b * US_STR + k) * 4u;
                asm volatile("cp.async.ca.shared.global [%0], [%1], 16;" :: "r"(dst), "l"(src));
            }
            asm volatile("cp.async.commit_group;");
        }

        float c0f[4] = {0, 0, 0, 0}, c1f[4] = {0, 0, 0, 0};

        // sub-chunk 0 ready -> mma kb 0..15 of this half
        asm volatile("cp.async.wait_group 1;");
        asm volatile("bar.sync %0, 128;" :: "r"(1 + khalf));
        #pragma unroll 4
        for (int kb = 0; kb < 16; kb++) {
            int o = khalf * 256 + kb * 8 + 2 * tig;
            uint2 ar0 = *(const uint2*)(hrow0 + o);
            uint2 ar1 = *(const uint2*)(hrow1 + o);
            uint2 bu0 = *(const uint2*)(urow0 + o);
            uint2 bu1 = *(const uint2*)(urow1 + o);
            mma8(c0f, ar0.x, ar1.x, ar0.y, ar1.y, bu0.x, bu0.y);
            mma8(c1f, ar0.x, ar1.x, ar0.y, ar1.y, bu1.x, bu1.y);
        }
        // sub-chunk 1 ready -> mma kb 16..31
        asm volatile("cp.async.wait_group 0;");
        asm volatile("bar.sync %0, 128;" :: "r"(1 + khalf));
        #pragma unroll 4
        for (int kb = 16; kb < 32; kb++) {
            int o = khalf * 256 + kb * 8 + 2 * tig;
            uint2 ar0 = *(const uint2*)(hrow0 + o);
            uint2 ar1 = *(const uint2*)(hrow1 + o);
            uint2 bu0 = *(const uint2*)(urow0 + o);
            uint2 bu1 = *(const uint2*)(urow1 + o);
            mma8(c0f, ar0.x, ar1.x, ar0.y, ar1.y, bu0.x, bu0.y);
            mma8(c1f, ar0.x, ar1.x, ar0.y, ar1.y, bu1.x, bu1.y);
        }

        // publish partial preactivations
        *(float2*)&gpb[r0 * GP_STR + g0 * 8 + 2 * tig]       = make_float2(c0f[0], c0f[1]);
        *(float2*)&gpb[(r0 + 8) * GP_STR + g0 * 8 + 2 * tig] = make_float2(c0f[2], c0f[3]);
        *(float2*)&gpb[r0 * GP_STR + g1 * 8 + 2 * tig]       = make_float2(c1f[0], c1f[1]);
        *(float2*)&gpb[(r0 + 8) * GP_STR + g1 * 8 + 2 * tig] = make_float2(c1f[2], c1f[3]);
        __syncthreads();

        // epilogue: reduce K-halves + xg, gates (i,f,c,o), state update, stores
        {
            const float* p0 = gp + eb * GP_STR;
            const float* p1 = gp + (32 + eb) * GP_STR;
            float iv = fsigm(xr[0] + p0[euu]       + p1[euu]);
            float fv = fsigm(xr[1] + p0[8 + euu]   + p1[8 + euu]);
            float cc = ftanh(xr[2] + p0[16 + euu]  + p1[16 + euu]);
            float ov = fsigm(xr[3] + p0[24 + euu]  + p1[24 + euu]);
            cst = fv * cst + iv * cc;
            float hv = ov * ftanh(cst);
            g_hbuf[dir][buf ^ 1][eb][u0 + ((euu & 3) << 1) + (euu >> 2)] =
                __uint_as_float(f2tf32(hv));
            if (dir == 0)
                out[((size_t)eb * T_SEQ + s) * U_DIM + u0 + euu] = hv;
            else
                g_hb_out[eb][tt][u0 + euu] = hv;
        }
        __syncthreads();

        // arrive (release h(s+1))
        if (tid == 0) {
            __threadfence();
            unsigned v = atomicAdd(&g_count[dir], 1u);
            if (v == NCTA_DIR - 1u) {
                g_count[dir] = 0u;
                __threadfence();
                g_epoch[dir] = ep0 + 2u + (unsigned)s;
            }
        }
    }
}

// =================================================================================
// Kernel C: out += backward outputs
// =================================================================================
__global__ void add_bwd(float* __restrict__ out)
{
    int i = blockIdx.x * blockDim.x + threadIdx.x;
    const int n4 = B_DIM * T_SEQ * U_DIM / 4;
    if (i < n4) {
        float4 a = ((float4*)out)[i];
        float4 b = ((const float4*)&g_hb_out[0][0][0])[i];
        a.x += b.x; a.y += b.y; a.z += b.z; a.w += b.w;
        ((float4*)out)[i] = a;
    }
}

// =================================================================================
extern "C" void kernel_launch(void* const* d_in, const int* in_sizes, int n_in,
                              void* d_out, int out_size)
{
    const float* x  = (const float*)d_in[0];
    const float* z  = (const float*)d_in[1];
    const float* Wf = (const float*)d_in[2];
    const float* Uf = (const float*)d_in[3];
    const float* bf = (const float*)d_in[4];
    const float* Wb = (const float*)d_in[5];
    const float* Ub = (const float*)d_in[6];
    const float* bb = (const float*)d_in[7];
    float* out = (float*)d_out;

    cudaFuncSetAttribute(lstm_rec, cudaFuncAttributeMaxDynamicSharedMemorySize, SMEM_REC);

    dim3 gg(M_TOT / 128, NG / 128, 2);
    gemm_xg<<<gg, 256>>>(x, Wf, bf, Wb, bb);
    lstm_rec<<<2 * NCTA_DIR, REC_THREADS, SMEM_REC>>>(z, Uf, Ub, out);
    add_bwd<<<(B_DIM * T_SEQ * U_DIM / 4 + 255) / 256, 256>>>(out);
}